// round 4
// baseline (speedup 1.0000x reference)
#include <cuda_runtime.h>
#include <cuda_bf16.h>
#include <cstdint>

// ---------------- problem constants ----------------
#define NN   4096      // total nodes (B*n)
#define HH   128       // hidden
#define BB   64        // graphs
#define NPG  64        // nodes per graph
#define E0C  131072    // input edges
#define NEC  135168    // edges incl self loops
#define KKC  52        // ceil(0.8*64)
#define NKC  3328      // B*KK
#define NSLOPE 0.01f

// output layout (floats)
#define OFF_XOUT 0
#define OFF_A2   (NKC*HH)                       // 425984
#define OFF_BATCH (OFF_A2 + (size_t)NKC*NKC)    // 11501568
#define OFF_PERM  (OFF_BATCH + NKC)             // 11504896

// ---------------- scratch layout (all 4-byte elems) ----------------
constexpr size_t O_DEG    = 0;
constexpr size_t O_DINV   = O_DEG + NN;
constexpr size_t O_CNTC   = O_DINV + NN;
constexpr size_t O_CNTR   = O_CNTC + NN;
constexpr size_t O_COLPTR = O_CNTR + NN;
constexpr size_t O_ROWPTR = O_COLPTR + NN + 4;
constexpr size_t O_COLCUR = O_ROWPTR + NN + 4;
constexpr size_t O_ROWCUR = O_COLCUR + NN;
constexpr size_t O_COLR   = O_ROWCUR + NN;
constexpr size_t O_COLEW  = O_COLR + NEC;
constexpr size_t O_ECOL   = O_COLEW + NEC;
constexpr size_t O_ROWC   = O_ECOL + NEC;
constexpr size_t O_ROWEW  = O_ROWC + NEC;
constexpr size_t O_ROWEP  = O_ROWEW + NEC;
constexpr size_t O_BUFA   = O_ROWEP + NEC;
constexpr size_t O_BUFH   = O_BUFA + (size_t)NN*128;
constexpr size_t O_T1     = O_BUFH + (size_t)NN*512;
constexpr size_t O_T2     = O_T1 + (size_t)NN*256;
constexpr size_t O_XQ     = O_T2 + (size_t)NN*128;
constexpr size_t O_TMP    = O_XQ + (size_t)NN*128;
constexpr size_t O_QT     = O_TMP + (size_t)NN*128;
constexpr size_t O_AGG    = O_QT + (size_t)NN*128;
constexpr size_t O_G0     = O_AGG + (size_t)NN*128;
constexpr size_t O_G1B    = O_G0 + (size_t)NN*128;
constexpr size_t O_XC     = O_G1B + (size_t)NN*128;
constexpr size_t O_XQ2    = O_XC + (size_t)NN*128;
constexpr size_t O_F1     = O_XQ2 + (size_t)NN*128;
constexpr size_t O_F2     = O_F1 + NN;
constexpr size_t O_G1S    = O_F2 + NN;
constexpr size_t O_G2S    = O_G1S + NN;
constexpr size_t O_SCORE  = O_G2S + NN;
constexpr size_t O_LOGIT  = O_SCORE + NN;
constexpr size_t O_PERM   = O_LOGIT + NN;
constexpr size_t O_POS    = O_PERM + NKC;
constexpr size_t O_MLOC   = O_POS + NN;
constexpr size_t SCRATCH_ELEMS = O_MLOC + (size_t)NN*KKC;

__device__ __align__(16) float d_scratch[SCRATCH_ELEMS];

__device__ __forceinline__ float lrelu(float v){ return v >= 0.f ? v : NSLOPE*v; }

// ---------------- small utility kernels ----------------
__global__ void zero_f(float* p, int n){
    int i = blockIdx.x*blockDim.x + threadIdx.x;
    for (; i < n; i += gridDim.x*blockDim.x) p[i] = 0.f;
}
__global__ void zero_i(int* p, int n){
    int i = blockIdx.x*blockDim.x + threadIdx.x;
    for (; i < n; i += gridDim.x*blockDim.x) p[i] = 0;
}
__global__ void zero_f4(float4* p, int n4){
    int i = blockIdx.x*blockDim.x + threadIdx.x;
    float4 z = make_float4(0.f,0.f,0.f,0.f);
    for (; i < n4; i += gridDim.x*blockDim.x) p[i] = z;
}

// ---------------- graph prep ----------------
__global__ void edge_pass1(const int* __restrict__ ei, const float* __restrict__ w,
                           float* deg, int* cntc, int* cntr){
    int e = blockIdx.x*blockDim.x + threadIdx.x;
    if (e >= NEC) return;
    int r, c; float wv;
    if (e < E0C){ r = ei[e]; c = ei[E0C + e]; wv = w[e]; }
    else        { r = c = e - E0C; wv = 1.f; }
    atomicAdd(&deg[c], wv);
    atomicAdd(&cntc[c], 1);
    atomicAdd(&cntr[r], 1);
}
__global__ void compute_dinv(const float* deg, float* dinv){
    int i = blockIdx.x*blockDim.x + threadIdx.x;
    if (i < NN) dinv[i] = rsqrtf(fmaxf(deg[i], 1e-12f));
}
__global__ void scan4096(const int* __restrict__ cnt, int* __restrict__ ptr, int* __restrict__ cur){
    __shared__ int sh[1024];
    int t = threadIdx.x;
    int v0 = cnt[4*t], v1 = cnt[4*t+1], v2 = cnt[4*t+2], v3 = cnt[4*t+3];
    int s = v0+v1+v2+v3;
    sh[t] = s;
    __syncthreads();
    for (int off = 1; off < 1024; off <<= 1){
        int xv = 0;
        if (t >= off) xv = sh[t-off];
        __syncthreads();
        if (t >= off) sh[t] += xv;
        __syncthreads();
    }
    int incl = sh[t];
    int base = incl - s;
    int p0 = base, p1 = base+v0, p2 = base+v0+v1, p3 = base+v0+v1+v2;
    ptr[4*t] = p0; ptr[4*t+1] = p1; ptr[4*t+2] = p2; ptr[4*t+3] = p3;
    cur[4*t] = p0; cur[4*t+1] = p1; cur[4*t+2] = p2; cur[4*t+3] = p3;
    if (t == 1023) ptr[4096] = incl;
}
__global__ void edge_scatter(const int* __restrict__ ei, const float* __restrict__ w,
                             const float* __restrict__ dinv,
                             int* colCur, int* rowCur,
                             int* colR, float* colEW,
                             int* rowC, float* rowEW, int* rowEp){
    int e = blockIdx.x*blockDim.x + threadIdx.x;
    if (e >= NEC) return;
    int r, c; float wv;
    if (e < E0C){ r = ei[e]; c = ei[E0C + e]; wv = w[e]; }
    else        { r = c = e - E0C; wv = 1.f; }
    float ewv = dinv[r]*wv*dinv[c];
    int p = atomicAdd(&colCur[c], 1);
    colR[p] = r; colEW[p] = ewv;
    int q = atomicAdd(&rowCur[r], 1);
    rowC[q] = c; rowEW[q] = ewv; rowEp[q] = p;
}

// out[c,:] = sum_{e in colCSR[c]} wv[e] * vin[colR[e],:]   (warp per node)
__global__ void gather_nodes(const float* __restrict__ vin, float* __restrict__ vout,
                             const int* __restrict__ ptr, const int* __restrict__ rows,
                             const float* __restrict__ wv){
    int node = blockIdx.x*8 + (threadIdx.x >> 5);
    int lane = threadIdx.x & 31;
    if (node >= NN) return;
    int s = ptr[node], e = ptr[node+1];
    float a0=0.f, a1=0.f, a2=0.f, a3=0.f;
    for (int p = s; p < e; p++){
        int r = rows[p]; float w = wv[p];
        const float* vr = vin + (size_t)r*HH;
        a0 = fmaf(w, vr[lane],      a0);
        a1 = fmaf(w, vr[lane+32],   a1);
        a2 = fmaf(w, vr[lane+64],   a2);
        a3 = fmaf(w, vr[lane+96],   a3);
    }
    float* vo = vout + (size_t)node*HH;
    vo[lane]=a0; vo[lane+32]=a1; vo[lane+64]=a2; vo[lane+96]=a3;
}

// ---------------- dense GEMM (fp32, 64x64 tile, 4x4 micro) ----------------
// C[M,N] = act(A[M,K] @ B[K,N]); requires M%64==0, N%64==0, K%16==0
__global__ void gemm64(const float* __restrict__ A, const float* __restrict__ B,
                       float* __restrict__ C, int M, int N, int K, int leaky){
    __shared__ __align__(16) float As[16][68];
    __shared__ __align__(16) float Bs[16][68];
    const int tid = threadIdx.x;
    const int tn = tid & 15;
    const int tm = tid >> 4;
    const int row0 = blockIdx.y*64;
    const int col0 = blockIdx.x*64;
    const int arow = tid >> 2;
    const int acol = (tid & 3) << 2;
    const int brow = tid >> 4;
    const int bcol = (tid & 15) << 2;
    float acc[4][4] = {};
    for (int k0 = 0; k0 < K; k0 += 16){
        float4 av = *(const float4*)(A + (size_t)(row0+arow)*K + k0 + acol);
        As[acol+0][arow]=av.x; As[acol+1][arow]=av.y; As[acol+2][arow]=av.z; As[acol+3][arow]=av.w;
        float4 bv = *(const float4*)(B + (size_t)(k0+brow)*N + col0 + bcol);
        Bs[brow][bcol+0]=bv.x; Bs[brow][bcol+1]=bv.y; Bs[brow][bcol+2]=bv.z; Bs[brow][bcol+3]=bv.w;
        __syncthreads();
        #pragma unroll
        for (int k = 0; k < 16; k++){
            float4 a4 = *(const float4*)&As[k][tm<<2];
            float4 b4 = *(const float4*)&Bs[k][tn<<2];
            float ar[4] = {a4.x,a4.y,a4.z,a4.w};
            float br[4] = {b4.x,b4.y,b4.z,b4.w};
            #pragma unroll
            for (int i2 = 0; i2 < 4; i2++)
                #pragma unroll
                for (int j2 = 0; j2 < 4; j2++)
                    acc[i2][j2] = fmaf(ar[i2], br[j2], acc[i2][j2]);
        }
        __syncthreads();
    }
    #pragma unroll
    for (int i2 = 0; i2 < 4; i2++){
        int r = row0 + (tm<<2) + i2;
        #pragma unroll
        for (int j2 = 0; j2 < 4; j2++){
            float v = acc[i2][j2];
            if (leaky && v < 0.f) v *= NSLOPE;
            C[(size_t)r*N + col0 + (tn<<2) + j2] = v;
        }
    }
}

// GEMV: out[i] = lrelu(A[i,:] dot w)  (K=128, warp per row)
__global__ void gemv_leaky(const float* __restrict__ A, const float* __restrict__ w,
                           float* __restrict__ out){
    int row  = blockIdx.x*8 + (threadIdx.x >> 5);
    int lane = threadIdx.x & 31;
    if (row >= NN) return;
    const float* ar = A + (size_t)row*128;
    float s = ar[lane]*w[lane] + ar[lane+32]*w[lane+32]
            + ar[lane+64]*w[lane+64] + ar[lane+96]*w[lane+96];
    #pragma unroll
    for (int o = 16; o; o >>= 1) s += __shfl_xor_sync(0xffffffffu, s, o);
    if (lane == 0) out[row] = lrelu(s);
}

// ---------------- attention helpers ----------------
__global__ void build_h(const float* __restrict__ a, const float* __restrict__ q,
                        float* __restrict__ h){
    int idx = blockIdx.x*blockDim.x + threadIdx.x;
    if (idx >= NN*HH) return;
    int i = idx >> 7, c = idx & 127;
    float av = a[idx], qv = q[idx];
    float* hr = h + (size_t)i*512;
    hr[c] = av; hr[128+c] = qv; hr[256+c] = av - qv; hr[384+c] = av * qv;
}
__global__ void build_qt(const float* __restrict__ tx, const int* __restrict__ bix,
                         float* __restrict__ qt){
    int idx = blockIdx.x*blockDim.x + threadIdx.x;
    if (idx >= NN*HH) return;
    int i = idx >> 7, c = idx & 127;
    qt[idx] = tx[(size_t)bix[i]*HH + c];
}
// softmax within each 64-node graph
__global__ void seg_softmax64(const float* __restrict__ in1, const float* __restrict__ in2,
                              float* __restrict__ out){
    __shared__ float sv[64];
    int b = blockIdx.x, t = threadIdx.x;
    int i = b*64 + t;
    float v = in1[i];
    if (in2) v += in2[i];
    sv[t] = v; __syncthreads();
    float m = -1e30f;
    #pragma unroll 8
    for (int j = 0; j < 64; j++) m = fmaxf(m, sv[j]);
    float e = expf(v - m);
    __syncthreads(); sv[t] = e; __syncthreads();
    float s = 0.f;
    #pragma unroll 8
    for (int j = 0; j < 64; j++) s += sv[j];
    out[i] = e / s;
}
// edge softmax per destination node (warp per node); writes normalized E in col-sorted order
__global__ void e_softmax(const int* __restrict__ colPtr, const int* __restrict__ colR,
                          const float* __restrict__ f1, const float* __restrict__ f2,
                          float* __restrict__ Ecol){
    int node = blockIdx.x*8 + (threadIdx.x >> 5);
    int lane = threadIdx.x & 31;
    if (node >= NN) return;
    int s = colPtr[node], e = colPtr[node+1];
    float f1c = f1[node];
    float mx = -1e30f;
    for (int p = s + lane; p < e; p += 32){
        float L = lrelu(f1c + f2[colR[p]]);
        mx = fmaxf(mx, L);
    }
    #pragma unroll
    for (int o = 16; o; o >>= 1) mx = fmaxf(mx, __shfl_xor_sync(0xffffffffu, mx, o));
    float sum = 0.f;
    for (int p = s + lane; p < e; p += 32){
        float L = lrelu(f1c + f2[colR[p]]);
        float ev = expf(L - mx);
        Ecol[p] = ev; sum += ev;
    }
    #pragma unroll
    for (int o = 16; o; o >>= 1) sum += __shfl_xor_sync(0xffffffffu, sum, o);
    for (int p = s + lane; p < e; p += 32) Ecol[p] = Ecol[p] / sum;
}
__global__ void xc_combine(const float* __restrict__ x, const float* __restrict__ g0,
                           const float* __restrict__ g1, float* __restrict__ xc){
    int idx = blockIdx.x*blockDim.x + threadIdx.x;
    if (idx >= NN*HH) return;
    float xv = x[idx];
    xc[idx] = 0.5f * (lrelu(xv + g0[idx]) + lrelu(xv + g1[idx]));
}

// ---------------- top-k (stable descending, jax semantics) ----------------
__global__ void topk_kernel(const float* __restrict__ score, int* __restrict__ perm,
                            int* __restrict__ pos){
    __shared__ float sv[64];
    int b = blockIdx.x, t = threadIdx.x;
    int i = b*64 + t;
    float s = score[i];
    sv[t] = s; __syncthreads();
    int rank = 0;
    for (int j = 0; j < 64; j++){
        float sj = sv[j];
        if (sj > s || (sj == s && j < t)) rank++;
    }
    pos[i] = (rank < KKC) ? b*KKC + rank : -1;
    if (rank < KKC) perm[b*KKC + rank] = i;
}
__global__ void write_xout(const float* __restrict__ x, const float* __restrict__ score,
                           const int* __restrict__ perm, float* __restrict__ out){
    int idx = blockIdx.x*blockDim.x + threadIdx.x;
    if (idx >= NKC*HH) return;
    int p = idx >> 7, c = idx & 127;
    int g = perm[p];
    out[OFF_XOUT + idx] = x[(size_t)g*HH + c] * score[g];
}
__global__ void write_misc(const int* __restrict__ perm, const int* __restrict__ bix,
                           float* __restrict__ out){
    int p = blockIdx.x*blockDim.x + threadIdx.x;
    if (p >= NKC) return;
    int g = perm[p];
    out[OFF_BATCH + p] = (float)bix[g];
    out[OFF_PERM  + p] = (float)g;
}

// ---------------- block-diagonal triple product ----------------
// M[i, kk] = sum_{e1: row=i} ew_e1 * sum_{e2: row=col_e1, pos[col_e2]=b*52+kk} E_e2
__global__ void spgemm_M(const int* __restrict__ rowPtr, const int* __restrict__ rowC,
                         const float* __restrict__ rowEW, const int* __restrict__ rowEp,
                         const float* __restrict__ Ecol, const int* __restrict__ pos,
                         float* __restrict__ Mloc){
    __shared__ float acc[KKC];
    int i = blockIdx.x;
    int tid = threadIdx.x;
    for (int t = tid; t < KKC; t += blockDim.x) acc[t] = 0.f;
    __syncthreads();
    int b52 = (i >> 6) * KKC;
    int s = rowPtr[i], e = rowPtr[i+1];
    int warp = tid >> 5, lane = tid & 31;
    for (int p = s + warp; p < e; p += 4){
        int j = rowC[p]; float ewv = rowEW[p];
        int s2 = rowPtr[j], e2 = rowPtr[j+1];
        for (int q = s2 + lane; q < e2; q += 32){
            int k = pos[rowC[q]];
            if (k >= 0){
                unsigned kk = (unsigned)(k - b52);
                if (kk < KKC) atomicAdd(&acc[kk], ewv * Ecol[rowEp[q]]);
            }
        }
    }
    __syncthreads();
    for (int t = tid; t < KKC; t += blockDim.x) Mloc[(size_t)i*KKC + t] = acc[t];
}
// A2[p, b*52+t] = sum_{e: col=perm[p]} E_e * M[row_e, t];  diag set to 1
__global__ void a2_rows(const int* __restrict__ colPtr, const int* __restrict__ colR,
                        const float* __restrict__ Ecol, const int* __restrict__ perm,
                        const float* __restrict__ Mloc, float* __restrict__ outA2){
    int p = blockIdx.x;
    int t = threadIdx.x;   // 64 threads, t<52 active
    int g = perm[p];
    int base = (g >> 6) * KKC;
    float acc = 0.f;
    int s = colPtr[g], e = colPtr[g+1];
    for (int q = s; q < e; q++){
        int r = colR[q]; float Ev = Ecol[q];
        if (t < KKC) acc = fmaf(Ev, Mloc[(size_t)r*KKC + t], acc);
    }
    if (t < KKC){
        float v = (base + t == p) ? 1.0f : acc;
        outA2[(size_t)p*NKC + base + t] = v;
    }
}

// ---------------- host launcher ----------------
extern "C" void kernel_launch(void* const* d_in, const int* in_sizes, int n_in,
                              void* d_out, int out_size){
    const float* x    = (const float*)d_in[0];
    const int*   ei   = (const int*)  d_in[1];
    const float* ewt  = (const float*)d_in[2];
    const float* tx   = (const float*)d_in[3];
    const int*   bix  = (const int*)  d_in[4];
    const float* Wk   = (const float*)d_in[5];
    const float* W1   = (const float*)d_in[6];
    const float* W2   = (const float*)d_in[7];
    const float* W3   = (const float*)d_in[8];
    const float* linW = (const float*)d_in[9];
    float* out = (float*)d_out;

    void* basep = nullptr;
    cudaGetSymbolAddress(&basep, d_scratch);
    float* base = (float*)basep;

    float* deg    = base + O_DEG;
    float* dinv   = base + O_DINV;
    int*   cntc   = (int*)(base + O_CNTC);
    int*   cntr   = (int*)(base + O_CNTR);
    int*   colPtr = (int*)(base + O_COLPTR);
    int*   rowPtr = (int*)(base + O_ROWPTR);
    int*   colCur = (int*)(base + O_COLCUR);
    int*   rowCur = (int*)(base + O_ROWCUR);
    int*   colR   = (int*)(base + O_COLR);
    float* colEW  = base + O_COLEW;
    float* Ecol   = base + O_ECOL;
    int*   rowC   = (int*)(base + O_ROWC);
    float* rowEW  = base + O_ROWEW;
    int*   rowEp  = (int*)(base + O_ROWEP);
    float* bufA   = base + O_BUFA;
    float* bufH   = base + O_BUFH;
    float* t1     = base + O_T1;
    float* t2     = base + O_T2;
    float* xq     = base + O_XQ;
    float* tmp    = base + O_TMP;
    float* qt     = base + O_QT;
    float* agg    = base + O_AGG;
    float* g0     = base + O_G0;
    float* g1b    = base + O_G1B;
    float* xc     = base + O_XC;
    float* xq2    = base + O_XQ2;
    float* f1     = base + O_F1;
    float* f2     = base + O_F2;
    float* g1s    = base + O_G1S;
    float* g2s    = base + O_G2S;
    float* score  = base + O_SCORE;
    float* logit  = base + O_LOGIT;
    int*   perm   = (int*)(base + O_PERM);
    int*   pos    = (int*)(base + O_POS);
    float* Mloc   = base + O_MLOC;

    const int EG = (NEC + 255)/256;   // 528

    // ---- graph prep ----
    zero_f<<<16,256>>>(deg, NN);
    zero_i<<<16,256>>>(cntc, NN);
    zero_i<<<16,256>>>(cntr, NN);
    edge_pass1<<<EG,256>>>(ei, ewt, deg, cntc, cntr);
    compute_dinv<<<16,256>>>(deg, dinv);
    scan4096<<<1,1024>>>(cntc, colPtr, colCur);
    scan4096<<<1,1024>>>(cntr, rowPtr, rowCur);
    edge_scatter<<<EG,256>>>(ei, ewt, dinv, colCur, rowCur, colR, colEW, rowC, rowEW, rowEp);

    // ---- x_q = hop(hop(x)) ----
    gather_nodes<<<512,256>>>(x,   tmp, colPtr, colR, colEW);
    gather_nodes<<<512,256>>>(tmp, xq,  colPtr, colR, colEW);
    build_qt<<<2048,256>>>(tx, bix, qt);

    // ---- attention helper ----
    auto attention = [&](const float* kv, const float* q, int widx, float* fout){
        gemm64<<<dim3(2,64),256>>>(kv, Wk + (size_t)widx*128*128, bufA, NN, 128, 128, 0);
        build_h<<<2048,256>>>(bufA, q, bufH);
        gemm64<<<dim3(4,64),256>>>(bufH, W1 + (size_t)widx*512*256, t1, NN, 256, 512, 1);
        gemm64<<<dim3(2,64),256>>>(t1,   W2 + (size_t)widx*256*128, t2, NN, 128, 256, 1);
        gemv_leaky<<<512,256>>>(t2, W3 + (size_t)widx*128, logit);
        seg_softmax64<<<64,64>>>(logit, (const float*)nullptr, fout);
    };

    attention(x, xq, 0, f1);
    attention(x, qt, 1, f2);

    // ---- edge attention softmax + aggregation ----
    e_softmax<<<512,256>>>(colPtr, colR, f1, f2, Ecol);
    gather_nodes<<<512,256>>>(x, agg, colPtr, colR, Ecol);
    gemm64<<<dim3(2,64),256>>>(agg, linW,                g0,  NN, 128, 128, 0);
    gemm64<<<dim3(2,64),256>>>(agg, linW + 128*128,      g1b, NN, 128, 128, 0);
    xc_combine<<<2048,256>>>(x, g0, g1b, xc);

    // ---- second round of attentions ----
    gather_nodes<<<512,256>>>(xc,  tmp, colPtr, colR, colEW);
    gather_nodes<<<512,256>>>(tmp, xq2, colPtr, colR, colEW);
    attention(xc, xq2, 2, g1s);
    attention(xc, qt,  3, g2s);
    seg_softmax64<<<64,64>>>(g1s, g2s, score);

    // ---- top-k + pooled outputs ----
    topk_kernel<<<64,64>>>(score, perm, pos);
    write_xout<<<(NKC*HH+255)/256,256>>>(x, score, perm, out);
    write_misc<<<(NKC+255)/256,256>>>(perm, bix, out);

    // ---- A2 = S_p^T (A_d S_p), block-diagonal ----
    zero_f4<<<2048,256>>>((float4*)(out + OFF_A2), (int)((size_t)NKC*NKC/4));
    spgemm_M<<<NN,128>>>(rowPtr, rowC, rowEW, rowEp, Ecol, pos, Mloc);
    a2_rows<<<NKC,64>>>(colPtr, colR, Ecol, perm, Mloc, out + OFF_A2);
}

// round 5
// speedup vs baseline: 1.1431x; 1.1431x over previous
#include <cuda_runtime.h>
#include <cuda_bf16.h>
#include <cstdint>

// ---------------- problem constants ----------------
#define NN   4096      // total nodes (B*n)
#define HH   128       // hidden
#define BB   64        // graphs
#define NPG  64        // nodes per graph
#define E0C  131072    // input edges
#define NEC  135168    // edges incl self loops
#define KKC  52        // ceil(0.8*64)
#define NKC  3328      // B*KK
#define NSLOPE 0.01f

// output layout (floats)
#define OFF_XOUT 0
#define OFF_A2   (NKC*HH)
#define OFF_BATCH (OFF_A2 + (size_t)NKC*NKC)
#define OFF_PERM  (OFF_BATCH + NKC)

// ---------------- scratch layout (all 4-byte elems) ----------------
constexpr size_t O_DEG    = 0;
constexpr size_t O_DINV   = (size_t)NN;
constexpr size_t O_CNTC   = (size_t)2*NN;
constexpr size_t O_CNTR   = (size_t)3*NN;
constexpr size_t O_COLPTR = (size_t)4*NN;
constexpr size_t O_ROWPTR = O_COLPTR + NN + 4;
constexpr size_t O_COLCUR = O_ROWPTR + NN + 4;
constexpr size_t O_ROWCUR = O_COLCUR + NN;
constexpr size_t O_COLR   = O_ROWCUR + NN;
constexpr size_t O_COLEW  = O_COLR + NEC;
constexpr size_t O_ECOL   = O_COLEW + NEC;
constexpr size_t O_ROWC   = O_ECOL + NEC;
constexpr size_t O_ROWEW  = O_ROWC + NEC;
constexpr size_t O_ROWEP  = O_ROWEW + NEC;
constexpr size_t O_ABUF   = O_ROWEP + NEC;                 // 2*NN*128
constexpr size_t O_H3     = O_ABUF + (size_t)2*NN*128;     // 2*NN*384
constexpr size_t O_T1     = O_H3   + (size_t)2*NN*384;     // 2*NN*256
constexpr size_t O_T2     = O_T1   + (size_t)2*NN*256;     // 2*NN*128
constexpr size_t O_XQ     = O_T2   + (size_t)2*NN*128;
constexpr size_t O_TMP    = O_XQ   + (size_t)NN*128;
constexpr size_t O_QT     = O_TMP  + (size_t)NN*128;
constexpr size_t O_AGG    = O_QT   + (size_t)NN*128;
constexpr size_t O_G0     = O_AGG  + (size_t)NN*128;       // 2*NN*128 (g0, g1b)
constexpr size_t O_XC     = O_G0   + (size_t)2*NN*128;
constexpr size_t O_XQ2    = O_XC   + (size_t)NN*128;
constexpr size_t O_F1     = O_XQ2  + (size_t)NN*128;
constexpr size_t O_F2     = O_F1 + NN;
constexpr size_t O_G1S    = O_F2 + NN;
constexpr size_t O_G2S    = O_G1S + NN;
constexpr size_t O_SCORE  = O_G2S + NN;
constexpr size_t O_PERM   = O_SCORE + NN;
constexpr size_t O_POS    = O_PERM + NKC;
constexpr size_t O_MLOC   = O_POS + NN;                    // NN*KKC
constexpr size_t O_W1E    = O_MLOC + (size_t)NN*KKC;       // 4*384*256
constexpr size_t SCRATCH_ELEMS = O_W1E + (size_t)4*384*256;

__device__ __align__(16) float d_scratch[SCRATCH_ELEMS];

__device__ __forceinline__ float lrelu(float v){ return v >= 0.f ? v : NSLOPE*v; }

// packed fp32x2 fma (Blackwell): acc = a*b + acc elementwise on 2 lanes
#define FMA2(accv, av, bv) \
    asm("fma.rn.f32x2 %0, %1, %2, %3;" : "=l"(accv) : "l"(av), "l"(bv), "l"(accv))

// ---------------- small utility kernels ----------------
__global__ void zero_prep(float* p, int n){  // zeroes deg/dinv/cntc/cntr region
    int i = blockIdx.x*blockDim.x + threadIdx.x;
    for (; i < n; i += gridDim.x*blockDim.x) p[i] = 0.f;
}

// ---------------- graph prep ----------------
__global__ void edge_pass1(const int* __restrict__ ei, const float* __restrict__ w,
                           float* deg, int* cntc, int* cntr){
    int e = blockIdx.x*blockDim.x + threadIdx.x;
    if (e >= NEC) return;
    int r, c; float wv;
    if (e < E0C){ r = ei[e]; c = ei[E0C + e]; wv = w[e]; }
    else        { r = c = e - E0C; wv = 1.f; }
    atomicAdd(&deg[c], wv);
    atomicAdd(&cntc[c], 1);
    atomicAdd(&cntr[r], 1);
}
__global__ void compute_dinv(const float* deg, float* dinv){
    int i = blockIdx.x*blockDim.x + threadIdx.x;
    if (i < NN) dinv[i] = rsqrtf(fmaxf(deg[i], 1e-12f));
}
__global__ void scan4096(const int* __restrict__ cnt, int* __restrict__ ptr, int* __restrict__ cur){
    __shared__ int sh[1024];
    int t = threadIdx.x;
    int v0 = cnt[4*t], v1 = cnt[4*t+1], v2 = cnt[4*t+2], v3 = cnt[4*t+3];
    int s = v0+v1+v2+v3;
    sh[t] = s;
    __syncthreads();
    for (int off = 1; off < 1024; off <<= 1){
        int xv = 0;
        if (t >= off) xv = sh[t-off];
        __syncthreads();
        if (t >= off) sh[t] += xv;
        __syncthreads();
    }
    int incl = sh[t];
    int base = incl - s;
    int p0 = base, p1 = base+v0, p2 = base+v0+v1, p3 = base+v0+v1+v2;
    ptr[4*t] = p0; ptr[4*t+1] = p1; ptr[4*t+2] = p2; ptr[4*t+3] = p3;
    cur[4*t] = p0; cur[4*t+1] = p1; cur[4*t+2] = p2; cur[4*t+3] = p3;
    if (t == 1023) ptr[4096] = incl;
}
__global__ void edge_scatter(const int* __restrict__ ei, const float* __restrict__ w,
                             const float* __restrict__ dinv,
                             int* colCur, int* rowCur,
                             int* colR, float* colEW,
                             int* rowC, float* rowEW, int* rowEp){
    int e = blockIdx.x*blockDim.x + threadIdx.x;
    if (e >= NEC) return;
    int r, c; float wv;
    if (e < E0C){ r = ei[e]; c = ei[E0C + e]; wv = w[e]; }
    else        { r = c = e - E0C; wv = 1.f; }
    float ewv = dinv[r]*wv*dinv[c];
    int p = atomicAdd(&colCur[c], 1);
    colR[p] = r; colEW[p] = ewv;
    int q = atomicAdd(&rowCur[r], 1);
    rowC[q] = c; rowEW[q] = ewv; rowEp[q] = p;
}

// W1eff[h] (384x256):  rows 0..127: W1[r]+W1[256+r]; 128..255: W1[r]-W1[r+128]; 256..383: W1[r+128]
__global__ void w1eff_prep(const float* __restrict__ W1, float* __restrict__ W1e){
    int idx = blockIdx.x*blockDim.x + threadIdx.x;
    const int TOT = 4*384*256;
    if (idx >= TOT) return;
    int h = idx / (384*256);
    int rem = idx - h*(384*256);
    int r = rem >> 8, c = rem & 255;
    const float* Wh = W1 + (size_t)h*512*256;
    float v;
    if (r < 128)       v = Wh[(size_t)r*256 + c] + Wh[(size_t)(256+r)*256 + c];
    else if (r < 256)  v = Wh[(size_t)r*256 + c] - Wh[(size_t)(r+128)*256 + c];
    else               v = Wh[(size_t)(r+128)*256 + c];
    W1e[idx] = v;
}

// out[c,:] = sum_{e in colCSR[c]} wv[e] * vin[colR[e],:]   (warp per node)
__global__ void gather_nodes(const float* __restrict__ vin, float* __restrict__ vout,
                             const int* __restrict__ ptr, const int* __restrict__ rows,
                             const float* __restrict__ wv){
    int node = blockIdx.x*8 + (threadIdx.x >> 5);
    int lane = threadIdx.x & 31;
    if (node >= NN) return;
    int s = ptr[node], e = ptr[node+1];
    float a0=0.f, a1=0.f, a2=0.f, a3=0.f;
    for (int p = s; p < e; p++){
        int r = rows[p]; float w = wv[p];
        const float* vr = vin + (size_t)r*HH;
        a0 = fmaf(w, vr[lane],      a0);
        a1 = fmaf(w, vr[lane+32],   a1);
        a2 = fmaf(w, vr[lane+64],   a2);
        a3 = fmaf(w, vr[lane+96],   a3);
    }
    float* vo = vout + (size_t)node*HH;
    vo[lane]=a0; vo[lane+32]=a1; vo[lane+64]=a2; vo[lane+96]=a3;
}

// ---------------- packed fp32x2 GEMM (64x64 tile, 4x4 micro, z-batched) ----------------
// C[M,N] = act(A[M,K] @ B[K,N]); M%64==0, N%64==0, K%16==0
__global__ __launch_bounds__(256) void gemm64p(
        const float* __restrict__ A, const float* __restrict__ B,
        float* __restrict__ C, int M, int N, int K, int leaky,
        size_t Astr, size_t Bstr, size_t Cstr){
    A += blockIdx.z*Astr; B += blockIdx.z*Bstr; C += blockIdx.z*Cstr;
    __shared__ __align__(16) float AsD[16][136];   // duplicated A: AsD[k][2m]=AsD[k][2m+1]=A[m]
    __shared__ __align__(16) float Bs[16][68];
    const int tid = threadIdx.x;
    const int tn = tid & 15;
    const int tm = tid >> 4;
    const int row0 = blockIdx.y*64;
    const int col0 = blockIdx.x*64;
    const int arow = tid >> 2;
    const int acol = (tid & 3) << 2;
    const int brow = tid >> 4;
    const int bcol = (tid & 15) << 2;
    unsigned long long acc[4][2];
    #pragma unroll
    for (int i = 0; i < 4; i++){ acc[i][0] = 0ull; acc[i][1] = 0ull; }
    for (int k0 = 0; k0 < K; k0 += 16){
        float4 av = *(const float4*)(A + (size_t)(row0+arow)*K + k0 + acol);
        *(float2*)&AsD[acol+0][2*arow] = make_float2(av.x, av.x);
        *(float2*)&AsD[acol+1][2*arow] = make_float2(av.y, av.y);
        *(float2*)&AsD[acol+2][2*arow] = make_float2(av.z, av.z);
        *(float2*)&AsD[acol+3][2*arow] = make_float2(av.w, av.w);
        float4 bv = *(const float4*)(B + (size_t)(k0+brow)*N + col0 + bcol);
        *(float4*)&Bs[brow][bcol] = bv;
        __syncthreads();
        #pragma unroll
        for (int k = 0; k < 16; k++){
            ulonglong2 aD0 = *reinterpret_cast<const ulonglong2*>(&AsD[k][tm*8]);
            ulonglong2 aD1 = *reinterpret_cast<const ulonglong2*>(&AsD[k][tm*8+4]);
            ulonglong2 bp  = *reinterpret_cast<const ulonglong2*>(&Bs[k][tn*4]);
            FMA2(acc[0][0], aD0.x, bp.x); FMA2(acc[0][1], aD0.x, bp.y);
            FMA2(acc[1][0], aD0.y, bp.x); FMA2(acc[1][1], aD0.y, bp.y);
            FMA2(acc[2][0], aD1.x, bp.x); FMA2(acc[2][1], aD1.x, bp.y);
            FMA2(acc[3][0], aD1.y, bp.x); FMA2(acc[3][1], aD1.y, bp.y);
        }
        __syncthreads();
    }
    #pragma unroll
    for (int i = 0; i < 4; i++){
        int r = row0 + (tm<<2) + i;
        #pragma unroll
        for (int jp = 0; jp < 2; jp++){
            union { unsigned long long u; float2 f; } cv;
            cv.u = acc[i][jp];
            float2 v = cv.f;
            if (leaky){
                v.x = v.x >= 0.f ? v.x : NSLOPE*v.x;
                v.y = v.y >= 0.f ? v.y : NSLOPE*v.y;
            }
            *(float2*)(C + (size_t)r*N + col0 + (tn<<2) + jp*2) = v;
        }
    }
}

// ---------------- attention helpers ----------------
// h3 = [a, q, a*q]  (per head via blockIdx.y)
__global__ void build_h3(const float* __restrict__ aab, const float* __restrict__ q0,
                         const float* __restrict__ q1, float* __restrict__ h3){
    int idx = blockIdx.x*blockDim.x + threadIdx.x;
    if (idx >= NN*HH) return;
    int head = blockIdx.y;
    const float* a = aab + (size_t)head*NN*128;
    const float* q = head ? q1 : q0;
    int i = idx >> 7, c = idx & 127;
    float av = a[idx], qv = q[idx];
    float* hr = h3 + (size_t)head*NN*384 + (size_t)i*384;
    hr[c] = av; hr[128+c] = qv; hr[256+c] = av * qv;
}
__global__ void build_qt(const float* __restrict__ tx, const int* __restrict__ bix,
                         float* __restrict__ qt){
    int idx = blockIdx.x*blockDim.x + threadIdx.x;
    if (idx >= NN*HH) return;
    int i = idx >> 7, c = idx & 127;
    qt[idx] = tx[(size_t)bix[i]*HH + c];
}
// fused: logit[i] = lrelu(t2[i,:] . W3) ; then segment-softmax over each 64-node graph.
// grid (BB, 2 heads), 256 threads
__global__ void mlp_tail(const float* __restrict__ t2b, const float* __restrict__ W3,
                         float* __restrict__ out0, float* __restrict__ out1){
    __shared__ float sv[64], se[64];
    int b = blockIdx.x, head = blockIdx.y;
    int tid = threadIdx.x;
    int wid = tid >> 5, lane = tid & 31;
    const float* A = t2b + (size_t)head*NN*128;
    const float* w = W3 + (size_t)head*128;
    float w0 = w[lane], w1 = w[lane+32], w2 = w[lane+64], w3v = w[lane+96];
    #pragma unroll
    for (int rr = 0; rr < 8; rr++){
        int node = wid*8 + rr;
        const float* ar = A + (size_t)(b*64 + node)*128;
        float s = ar[lane]*w0 + ar[lane+32]*w1 + ar[lane+64]*w2 + ar[lane+96]*w3v;
        #pragma unroll
        for (int o = 16; o; o >>= 1) s += __shfl_xor_sync(0xffffffffu, s, o);
        if (lane == 0) sv[node] = lrelu(s);
    }
    __syncthreads();
    float e = 0.f, v = 0.f;
    if (tid < 64){
        v = sv[tid];
        float m = -1e30f;
        #pragma unroll 8
        for (int j = 0; j < 64; j++) m = fmaxf(m, sv[j]);
        e = expf(v - m);
        se[tid] = e;
    }
    __syncthreads();
    if (tid < 64){
        float s = 0.f;
        #pragma unroll 8
        for (int j = 0; j < 64; j++) s += se[j];
        float* out = head ? out1 : out0;
        out[b*64 + tid] = e / s;
    }
}
// softmax within each 64-node graph (sum of two logit arrays)
__global__ void seg_softmax64(const float* __restrict__ in1, const float* __restrict__ in2,
                              float* __restrict__ out){
    __shared__ float sv[64];
    int b = blockIdx.x, t = threadIdx.x;
    int i = b*64 + t;
    float v = in1[i] + in2[i];
    sv[t] = v; __syncthreads();
    float m = -1e30f;
    #pragma unroll 8
    for (int j = 0; j < 64; j++) m = fmaxf(m, sv[j]);
    float e = expf(v - m);
    __syncthreads(); sv[t] = e; __syncthreads();
    float s = 0.f;
    #pragma unroll 8
    for (int j = 0; j < 64; j++) s += sv[j];
    out[i] = e / s;
}
// edge softmax per destination node (warp per node)
__global__ void e_softmax(const int* __restrict__ colPtr, const int* __restrict__ colR,
                          const float* __restrict__ f1, const float* __restrict__ f2,
                          float* __restrict__ Ecol){
    int node = blockIdx.x*8 + (threadIdx.x >> 5);
    int lane = threadIdx.x & 31;
    if (node >= NN) return;
    int s = colPtr[node], e = colPtr[node+1];
    float f1c = f1[node];
    float mx = -1e30f;
    for (int p = s + lane; p < e; p += 32){
        float L = lrelu(f1c + f2[colR[p]]);
        mx = fmaxf(mx, L);
    }
    #pragma unroll
    for (int o = 16; o; o >>= 1) mx = fmaxf(mx, __shfl_xor_sync(0xffffffffu, mx, o));
    float sum = 0.f;
    for (int p = s + lane; p < e; p += 32){
        float L = lrelu(f1c + f2[colR[p]]);
        float ev = expf(L - mx);
        Ecol[p] = ev; sum += ev;
    }
    #pragma unroll
    for (int o = 16; o; o >>= 1) sum += __shfl_xor_sync(0xffffffffu, sum, o);
    for (int p = s + lane; p < e; p += 32) Ecol[p] = Ecol[p] / sum;
}
__global__ void xc_combine(const float* __restrict__ x, const float* __restrict__ g0,
                           const float* __restrict__ g1, float* __restrict__ xc){
    int idx = blockIdx.x*blockDim.x + threadIdx.x;
    if (idx >= NN*HH) return;
    float xv = x[idx];
    xc[idx] = 0.5f * (lrelu(xv + g0[idx]) + lrelu(xv + g1[idx]));
}

// ---------------- top-k (stable descending, jax semantics) ----------------
__global__ void topk_kernel(const float* __restrict__ score, int* __restrict__ perm,
                            int* __restrict__ pos, const int* __restrict__ bix,
                            float* __restrict__ out){
    __shared__ float sv[64];
    int b = blockIdx.x, t = threadIdx.x;
    int i = b*64 + t;
    float s = score[i];
    sv[t] = s; __syncthreads();
    int rank = 0;
    for (int j = 0; j < 64; j++){
        float sj = sv[j];
        if (sj > s || (sj == s && j < t)) rank++;
    }
    pos[i] = (rank < KKC) ? b*KKC + rank : -1;
    if (rank < KKC){
        int p = b*KKC + rank;
        perm[p] = i;
        out[OFF_BATCH + p] = (float)bix[i];
        out[OFF_PERM  + p] = (float)i;
    }
}
__global__ void write_xout(const float* __restrict__ x, const float* __restrict__ score,
                           const int* __restrict__ perm, float* __restrict__ out){
    int idx = blockIdx.x*blockDim.x + threadIdx.x;
    if (idx >= NKC*HH) return;
    int p = idx >> 7, c = idx & 127;
    int g = perm[p];
    out[OFF_XOUT + idx] = x[(size_t)g*HH + c] * score[g];
}

// ---------------- block-diagonal triple product ----------------
__global__ void spgemm_M(const int* __restrict__ rowPtr, const int* __restrict__ rowC,
                         const float* __restrict__ rowEW, const int* __restrict__ rowEp,
                         const float* __restrict__ Ecol, const int* __restrict__ pos,
                         float* __restrict__ Mloc){
    __shared__ float acc[KKC];
    int i = blockIdx.x;
    int tid = threadIdx.x;
    for (int t = tid; t < KKC; t += blockDim.x) acc[t] = 0.f;
    __syncthreads();
    int b52 = (i >> 6) * KKC;
    int s = rowPtr[i], e = rowPtr[i+1];
    int warp = tid >> 5, lane = tid & 31;
    for (int p = s + warp; p < e; p += 4){
        int j = rowC[p]; float ewv = rowEW[p];
        int s2 = rowPtr[j], e2 = rowPtr[j+1];
        for (int q = s2 + lane; q < e2; q += 32){
            int k = pos[rowC[q]];
            if (k >= 0){
                unsigned kk = (unsigned)(k - b52);
                if (kk < KKC) atomicAdd(&acc[kk], ewv * Ecol[rowEp[q]]);
            }
        }
    }
    __syncthreads();
    for (int t = tid; t < KKC; t += blockDim.x) Mloc[(size_t)i*KKC + t] = acc[t];
}
// writes FULL A2 row (zeros outside the diagonal band) — fuses the zero-fill.
__global__ void a2_full(const int* __restrict__ colPtr, const int* __restrict__ colR,
                        const float* __restrict__ Ecol, const int* __restrict__ perm,
                        const float* __restrict__ Mloc, float* __restrict__ outA2){
    __shared__ float acc[KKC];
    int p = blockIdx.x;
    int tid = threadIdx.x;   // 256
    int g = perm[p];
    int base = (g >> 6) * KKC;
    if (tid < KKC){
        float a = 0.f;
        int s = colPtr[g], e = colPtr[g+1];
        for (int q = s; q < e; q++)
            a = fmaf(Ecol[q], Mloc[(size_t)colR[q]*KKC + tid], a);
        acc[tid] = a;
    }
    __syncthreads();
    float* row = outA2 + (size_t)p*NKC;
    for (int t = tid; t < NKC; t += 256){
        unsigned kk = (unsigned)(t - base);
        float v = (kk < KKC) ? acc[kk] : 0.f;
        if (t == p) v = 1.0f;
        row[t] = v;
    }
}

// ---------------- host launcher ----------------
extern "C" void kernel_launch(void* const* d_in, const int* in_sizes, int n_in,
                              void* d_out, int out_size){
    const float* x    = (const float*)d_in[0];
    const int*   ei   = (const int*)  d_in[1];
    const float* ewt  = (const float*)d_in[2];
    const float* tx   = (const float*)d_in[3];
    const int*   bix  = (const int*)  d_in[4];
    const float* Wk   = (const float*)d_in[5];
    const float* W1   = (const float*)d_in[6];
    const float* W2   = (const float*)d_in[7];
    const float* W3   = (const float*)d_in[8];
    const float* linW = (const float*)d_in[9];
    float* out = (float*)d_out;

    void* basep = nullptr;
    cudaGetSymbolAddress(&basep, d_scratch);
    float* base = (float*)basep;

    float* deg    = base + O_DEG;
    float* dinv   = base + O_DINV;
    int*   cntc   = (int*)(base + O_CNTC);
    int*   cntr   = (int*)(base + O_CNTR);
    int*   colPtr = (int*)(base + O_COLPTR);
    int*   rowPtr = (int*)(base + O_ROWPTR);
    int*   colCur = (int*)(base + O_COLCUR);
    int*   rowCur = (int*)(base + O_ROWCUR);
    int*   colR   = (int*)(base + O_COLR);
    float* colEW  = base + O_COLEW;
    float* Ecol   = base + O_ECOL;
    int*   rowC   = (int*)(base + O_ROWC);
    float* rowEW  = base + O_ROWEW;
    int*   rowEp  = (int*)(base + O_ROWEP);
    float* aab    = base + O_ABUF;
    float* h3     = base + O_H3;
    float* t1     = base + O_T1;
    float* t2     = base + O_T2;
    float* xq     = base + O_XQ;
    float* tmp    = base + O_TMP;
    float* qt     = base + O_QT;
    float* agg    = base + O_AGG;
    float* g0     = base + O_G0;
    float* g1b    = g0 + (size_t)NN*128;
    float* xc     = base + O_XC;
    float* xq2    = base + O_XQ2;
    float* f1     = base + O_F1;
    float* f2     = base + O_F2;
    float* g1s    = base + O_G1S;
    float* g2s    = base + O_G2S;
    float* score  = base + O_SCORE;
    int*   perm   = (int*)(base + O_PERM);
    int*   pos    = (int*)(base + O_POS);
    float* Mloc   = base + O_MLOC;
    float* W1e    = base + O_W1E;

    const int EG = (NEC + 255)/256;
    const size_t S128 = (size_t)NN*128;

    // ---- graph prep ----
    zero_prep<<<16,256>>>(deg, 4*NN);    // deg + dinv + cntc + cntr region
    edge_pass1<<<EG,256>>>(ei, ewt, deg, cntc, cntr);
    compute_dinv<<<16,256>>>(deg, dinv);
    scan4096<<<1,1024>>>(cntc, colPtr, colCur);
    scan4096<<<1,1024>>>(cntr, rowPtr, rowCur);
    edge_scatter<<<EG,256>>>(ei, ewt, dinv, colCur, rowCur, colR, colEW, rowC, rowEW, rowEp);
    w1eff_prep<<<(4*384*256+255)/256,256>>>(W1, W1e);

    // ---- x_q = hop(hop(x)) ----
    gather_nodes<<<512,256>>>(x,   tmp, colPtr, colR, colEW);
    gather_nodes<<<512,256>>>(tmp, xq,  colPtr, colR, colEW);
    build_qt<<<2048,256>>>(tx, bix, qt);

    // ---- attention pair (2 heads batched over blockIdx.z) ----
    auto attention_pair = [&](const float* kv, const float* q0, const float* q1,
                              int pairbase, float* out0, float* out1){
        // a_h = kv @ Wk[h]
        gemm64p<<<dim3(2,64,2),256>>>(kv, Wk + (size_t)pairbase*128*128, aab,
                                      NN, 128, 128, 0, 0, (size_t)128*128, S128);
        build_h3<<<dim3(2048,2),256>>>(aab, q0, q1, h3);
        // t1_h = lrelu(h3_h @ W1e[h])   K=384
        gemm64p<<<dim3(4,64,2),256>>>(h3, W1e + (size_t)pairbase*384*256, t1,
                                      NN, 256, 384, 1, (size_t)NN*384, (size_t)384*256, (size_t)NN*256);
        // t2_h = lrelu(t1_h @ W2[h])    K=256
        gemm64p<<<dim3(2,64,2),256>>>(t1, W2 + (size_t)pairbase*256*128, t2,
                                      NN, 128, 256, 1, (size_t)NN*256, (size_t)256*128, S128);
        mlp_tail<<<dim3(BB,2),256>>>(t2, W3 + (size_t)pairbase*128, out0, out1);
    };

    attention_pair(x, xq, qt, 0, f1, f2);

    // ---- edge attention softmax + aggregation ----
    e_softmax<<<512,256>>>(colPtr, colR, f1, f2, Ecol);
    gather_nodes<<<512,256>>>(x, agg, colPtr, colR, Ecol);
    gemm64p<<<dim3(2,64,2),256>>>(agg, linW, g0, NN, 128, 128, 0,
                                  0, (size_t)128*128, S128);
    xc_combine<<<2048,256>>>(x, g0, g1b, xc);

    // ---- second round ----
    gather_nodes<<<512,256>>>(xc,  tmp, colPtr, colR, colEW);
    gather_nodes<<<512,256>>>(tmp, xq2, colPtr, colR, colEW);
    attention_pair(xc, xq2, qt, 2, g1s, g2s);
    seg_softmax64<<<BB,64>>>(g1s, g2s, score);

    // ---- top-k + pooled outputs ----
    topk_kernel<<<BB,64>>>(score, perm, pos, bix, out);
    write_xout<<<(NKC*HH+255)/256,256>>>(x, score, perm, out);

    // ---- A2 = S_p^T (A_d S_p), block-diagonal ----
    spgemm_M<<<NN,128>>>(rowPtr, rowC, rowEW, rowEp, Ecol, pos, Mloc);
    a2_full<<<NKC,256>>>(colPtr, colR, Ecol, perm, Mloc, out + OFF_A2);
}